// round 5
// baseline (speedup 1.0000x reference)
#include <cuda_runtime.h>
#include <cuda_bf16.h>
#include <math.h>

// Problem constants
#define B 4
#define T 512
#define C 256
#define C2 512
#define HEADS 4
#define MAXOFF 2

#define TI 32          // i-tile per block (rep)
#define TJ 32          // j-tile per block (rep)
#define NJT (T / TJ)   // 16 j-tiles
#define CK 128         // c chunk (rep)

typedef unsigned long long u64;

// Scratch (allocation-free: device globals)
__device__ float g_subj[B * T * C];
__device__ float g_obj[B * T * C];
__device__ float g_part[B * T * NJT * HEADS];   // partial exp-sums per j-tile

// packed f32x2 helpers
static __device__ __forceinline__ u64 add2(u64 a, u64 b) {
    u64 r; asm("add.rn.f32x2 %0, %1, %2;" : "=l"(r) : "l"(a), "l"(b)); return r;
}
static __device__ __forceinline__ u64 fma2(u64 a, u64 b, u64 c) {
    u64 r; asm("fma.rn.f32x2 %0, %1, %2, %3;" : "=l"(r) : "l"(a), "l"(b), "l"(c)); return r;
}
static __device__ __forceinline__ float2 unpack2(u64 v) {
    float2 r; asm("mov.b64 {%0, %1}, %2;" : "=f"(r.x), "=f"(r.y) : "l"(v)); return r;
}
#define FABS2(v) ((v) & 0x7fffffff7fffffffULL)

// ---------------------------------------------------------------------------
// Kernel 1: max-pool along channel (window 5, pad 2) + concat -> x_new
// ---------------------------------------------------------------------------
__global__ void pool_concat_kernel(const float* __restrict__ x,
                                   float* __restrict__ xnew) {
    int idx = blockIdx.x * 256 + threadIdx.x;
    if (idx >= B * T * C2) return;
    int cc = idx & (C2 - 1);
    int bt = idx >> 9;
    const float* xr = x + bt * C;
    float v;
    if (cc < C) {
        int lo = cc - MAXOFF; if (lo < 0) lo = 0;
        int hi = cc + MAXOFF; if (hi > C - 1) hi = C - 1;
        v = -INFINITY;
        #pragma unroll 5
        for (int c = lo; c <= hi; c++) v = fmaxf(v, xr[c]);
    } else {
        v = xr[cc - C];
    }
    xnew[idx] = v;
}

// ---------------------------------------------------------------------------
// Kernel 2: projection GEMMs, n-packed f32x2.
// Tile 64m x 32n, 128 threads (tx 0..7 = n-quad, ty 0..15 = m-quad).
// A duplicated in smem ([k][2m]) so fma2 operands need no packing MOVs.
// ---------------------------------------------------------------------------
#define GPAD 132
__global__ void __launch_bounds__(128)
gemm_kernel(const float* __restrict__ A,
            const float* __restrict__ W0,
            const float* __restrict__ b0,
            const float* __restrict__ W1,
            const float* __restrict__ b1,
            float* __restrict__ out0,
            float* __restrict__ out1) {
    __shared__ float As2[16 * GPAD];   // [k][2m] duplicated, row 132 floats
    __shared__ float Ws[16 * 36];      // [k][n], row 36 floats

    const float* W    = blockIdx.z ? W1 : W0;
    const float* bias = blockIdx.z ? b1 : b0;
    float* out        = blockIdx.z ? out1 : out0;

    const int tid = threadIdx.x;
    const int tx = tid & 7;            // n-quad: n0 = 4*tx
    const int ty = tid >> 3;           // m-quad: m0 = 4*ty
    const int bm = blockIdx.y * 64;
    const int bn = blockIdx.x * 32;

    u64 acc[4][2];
    #pragma unroll
    for (int m = 0; m < 4; m++) { acc[m][0] = 0ULL; acc[m][1] = 0ULL; }

    const int lm = tid >> 2;           // loader m (0..31), +32 on second iter
    const int lkq = tid & 3;           // loader k-quad
    const int wk = tid >> 3;           // W loader k
    const int wnq = tid & 7;           // W loader n-quad

    for (int k0 = 0; k0 < C2; k0 += 16) {
        // A chunk: 64m x 16k, duplicated into As2[k][2m]
        #pragma unroll
        for (int l = 0; l < 2; l++) {
            int m = lm + l * 32;
            float4 av = *(const float4*)&A[(bm + m) * C2 + k0 + 4 * lkq];
            float2* d0 = (float2*)&As2[(4 * lkq + 0) * GPAD + 2 * m];
            float2* d1 = (float2*)&As2[(4 * lkq + 1) * GPAD + 2 * m];
            float2* d2 = (float2*)&As2[(4 * lkq + 2) * GPAD + 2 * m];
            float2* d3 = (float2*)&As2[(4 * lkq + 3) * GPAD + 2 * m];
            *d0 = make_float2(av.x, av.x);
            *d1 = make_float2(av.y, av.y);
            *d2 = make_float2(av.z, av.z);
            *d3 = make_float2(av.w, av.w);
        }
        // W chunk: 16k x 32n
        {
            float4 wv = *(const float4*)&W[(k0 + wk) * C + bn + 4 * wnq];
            *(float4*)&Ws[wk * 36 + 4 * wnq] = wv;
        }
        __syncthreads();

        #pragma unroll
        for (int k = 0; k < 16; k++) {
            ulonglong2 A0 = *(const ulonglong2*)&As2[k * GPAD + 8 * ty];
            ulonglong2 A1 = *(const ulonglong2*)&As2[k * GPAD + 8 * ty + 4];
            ulonglong2 Wv = *(const ulonglong2*)&Ws[k * 36 + 4 * tx];
            acc[0][0] = fma2(A0.x, Wv.x, acc[0][0]);
            acc[0][1] = fma2(A0.x, Wv.y, acc[0][1]);
            acc[1][0] = fma2(A0.y, Wv.x, acc[1][0]);
            acc[1][1] = fma2(A0.y, Wv.y, acc[1][1]);
            acc[2][0] = fma2(A1.x, Wv.x, acc[2][0]);
            acc[2][1] = fma2(A1.x, Wv.y, acc[2][1]);
            acc[3][0] = fma2(A1.y, Wv.x, acc[3][0]);
            acc[3][1] = fma2(A1.y, Wv.y, acc[3][1]);
        }
        __syncthreads();
    }

    u64 bv0 = *(const u64*)&bias[bn + 4 * tx];
    u64 bv1 = *(const u64*)&bias[bn + 4 * tx + 2];
    #pragma unroll
    for (int m = 0; m < 4; m++) {
        ulonglong2 r;
        r.x = add2(acc[m][0], bv0);
        r.y = add2(acc[m][1], bv1);
        *(ulonglong2*)&out[(bm + 4 * ty + m) * C + bn + 4 * tx] = r;
    }
}

// ---------------------------------------------------------------------------
// Kernel 3a: e = exp(relu(rep)) for a 32x32 (i,j) tile.
// 64 threads = 8 tx (j, stride-8) x 8 ty (i, stride-8).
// Microtile 4i x 4j x 4h; c packed f32x2. Swizzled conflict-free smem.
// ---------------------------------------------------------------------------
__global__ void __launch_bounds__(64)
rep_exp_kernel(const float* __restrict__ subj,
               const float* __restrict__ obj,
               const float* __restrict__ W_t,
               const float* __restrict__ b_t,
               float* __restrict__ attn,
               float* __restrict__ part) {
    __shared__ float s_sh[TJ * CK];     // [jrow][c], swizzled
    __shared__ float o_sh[TI * CK];     // [irow][c], swizzled, holds -obj
    __shared__ float w_sh[HEADS * C];   // [h][c]

    const int tid = threadIdx.x;
    const int tx = tid & 7;            // j
    const int ty = tid >> 3;           // i (0..7)
    const int jt = blockIdx.x;
    const int j0 = jt * TJ;
    const int i0 = blockIdx.y * TI;
    const int b  = blockIdx.z;

    // Load W_t transposed: w_sh[h][c] = W_t[c*4+h]
    #pragma unroll
    for (int c = tid; c < C; c += 64) {
        float4 wv = *(const float4*)&W_t[c * 4];
        w_sh[0 * C + c] = wv.x;
        w_sh[1 * C + c] = wv.y;
        w_sh[2 * C + c] = wv.z;
        w_sh[3 * C + c] = wv.w;
    }

    u64 acc[4][4][4];
    #pragma unroll
    for (int p = 0; p < 4; p++)
        #pragma unroll
        for (int q = 0; q < 4; q++)
            #pragma unroll
            for (int h = 0; h < 4; h++) acc[p][q][h] = 0ULL;

    const float* sp[4];
    const float* op[4];
    #pragma unroll
    for (int q = 0; q < 4; q++) sp[q] = s_sh + (tx + 8 * q) * CK;
    #pragma unroll
    for (int p = 0; p < 4; p++) op[p] = o_sh + (ty + 8 * p) * CK;

    for (int ck = 0; ck < C / CK; ck++) {
        const int cbase = ck * CK;
        // load s/o chunk (32 rows x 128 c), coalesced gmem, swizzled smem
        #pragma unroll
        for (int l = 0; l < 16; l++) {
            int t = tid + l * 64;
            int row = t >> 5;          // 0..31
            int ccg = t & 31;          // 16B group within chunk
            int phys = (ccg ^ (row & 7)) << 2;
            float4 sv = *(const float4*)&subj[(b * T + j0 + row) * C + cbase + ccg * 4];
            *(float4*)&s_sh[row * CK + phys] = sv;
            float4 ov = *(const float4*)&obj[(b * T + i0 + row) * C + cbase + ccg * 4];
            ov.x = -ov.x; ov.y = -ov.y; ov.z = -ov.z; ov.w = -ov.w;
            *(float4*)&o_sh[row * CK + phys] = ov;
        }
        __syncthreads();

        const float* wp0 = w_sh + 0 * C + cbase;
        const float* wp1 = w_sh + 1 * C + cbase;
        const float* wp2 = w_sh + 2 * C + cbase;
        const float* wp3 = w_sh + 3 * C + cbase;

        #pragma unroll 1
        for (int g = 0; g < CK / 4; g++) {
            const int gs = (g ^ tx) << 2;
            const int gi = (g ^ ty) << 2;
            ulonglong2 S[4], P[4], Wv[4];
            #pragma unroll
            for (int q = 0; q < 4; q++) S[q] = *(const ulonglong2*)(sp[q] + gs);
            #pragma unroll
            for (int p = 0; p < 4; p++) P[p] = *(const ulonglong2*)(op[p] + gi);
            Wv[0] = *(const ulonglong2*)(wp0 + g * 4);
            Wv[1] = *(const ulonglong2*)(wp1 + g * 4);
            Wv[2] = *(const ulonglong2*)(wp2 + g * 4);
            Wv[3] = *(const ulonglong2*)(wp3 + g * 4);

            #pragma unroll
            for (int p = 0; p < 4; p++) {
                #pragma unroll
                for (int q = 0; q < 4; q++) {
                    u64 a0 = FABS2(add2(S[q].x, P[p].x));
                    acc[p][q][0] = fma2(a0, Wv[0].x, acc[p][q][0]);
                    acc[p][q][1] = fma2(a0, Wv[1].x, acc[p][q][1]);
                    acc[p][q][2] = fma2(a0, Wv[2].x, acc[p][q][2]);
                    acc[p][q][3] = fma2(a0, Wv[3].x, acc[p][q][3]);
                    u64 a1 = FABS2(add2(S[q].y, P[p].y));
                    acc[p][q][0] = fma2(a1, Wv[0].y, acc[p][q][0]);
                    acc[p][q][1] = fma2(a1, Wv[1].y, acc[p][q][1]);
                    acc[p][q][2] = fma2(a1, Wv[2].y, acc[p][q][2]);
                    acc[p][q][3] = fma2(a1, Wv[3].y, acc[p][q][3]);
                }
            }
        }
        __syncthreads();
    }

    // Epilogue: z = relu(sum + bias), e = exp(z); write e; per-i partial sums
    const float4 btv = *(const float4*)b_t;

    #pragma unroll
    for (int p = 0; p < 4; p++) {
        int i = i0 + ty + 8 * p;
        float4 ps = make_float4(0.f, 0.f, 0.f, 0.f);
        #pragma unroll
        for (int q = 0; q < 4; q++) {
            int j = j0 + tx + 8 * q;
            float2 f0 = unpack2(acc[p][q][0]);
            float2 f1 = unpack2(acc[p][q][1]);
            float2 f2 = unpack2(acc[p][q][2]);
            float2 f3 = unpack2(acc[p][q][3]);
            float4 ev;
            ev.x = __expf(fmaxf(f0.x + f0.y + btv.x, 0.0f));
            ev.y = __expf(fmaxf(f1.x + f1.y + btv.y, 0.0f));
            ev.z = __expf(fmaxf(f2.x + f2.y + btv.z, 0.0f));
            ev.w = __expf(fmaxf(f3.x + f3.y + btv.w, 0.0f));
            *(float4*)&attn[(((size_t)(b * T + i)) * T + j) * HEADS] = ev;
            ps.x += ev.x; ps.y += ev.y; ps.z += ev.z; ps.w += ev.w;
        }
        // reduce across tx (8 lanes, stride 1 within warp)
        #pragma unroll
        for (int m = 4; m >= 1; m >>= 1) {
            ps.x += __shfl_xor_sync(0xffffffffu, ps.x, m);
            ps.y += __shfl_xor_sync(0xffffffffu, ps.y, m);
            ps.z += __shfl_xor_sync(0xffffffffu, ps.z, m);
            ps.w += __shfl_xor_sync(0xffffffffu, ps.w, m);
        }
        if (tx == 0)
            *(float4*)&part[((size_t)(b * T + i) * NJT + jt) * HEADS] = ps;
    }
}

// ---------------------------------------------------------------------------
// Kernel 3b: fused denominator + normalize + mask. One block per (b,i).
// ---------------------------------------------------------------------------
__global__ void __launch_bounds__(128)
normalize_kernel(const float* __restrict__ part,
                 const int* __restrict__ mask,
                 float* __restrict__ attn) {
    __shared__ float sinv[4];
    const int bi = blockIdx.x;         // b*T + i
    const int tid = threadIdx.x;

    if (tid < 4) {
        float s = 0.f;
        #pragma unroll
        for (int jt = 0; jt < NJT; jt++)
            s += part[((size_t)bi * NJT + jt) * HEADS + tid];
        sinv[tid] = 1.0f / s;
    }
    __syncthreads();

    const float4 iv = make_float4(sinv[0], sinv[1], sinv[2], sinv[3]);
    const int mi = mask[bi];
    const int b = bi >> 9;
    float4* arow = (float4*)attn + (size_t)bi * T;

    #pragma unroll
    for (int r = 0; r < 4; r++) {
        int j = tid + r * 128;
        float4 v = arow[j];
        int mj = mask[b * T + j];
        float kill = (mi && mj) ? 0.0f : 1.0f;
        v.x *= iv.x * kill;
        v.y *= iv.y * kill;
        v.z *= iv.z * kill;
        v.w *= iv.w * kill;
        arow[j] = v;
    }
}

// ---------------------------------------------------------------------------
extern "C" void kernel_launch(void* const* d_in, const int* in_sizes, int n_in,
                              void* d_out, int out_size) {
    const float* x      = (const float*)d_in[0];
    const float* W_subj = (const float*)d_in[1];
    const float* b_subj = (const float*)d_in[2];
    const float* W_obj  = (const float*)d_in[3];
    const float* b_obj  = (const float*)d_in[4];
    const float* W_t    = (const float*)d_in[5];
    const float* b_t    = (const float*)d_in[6];
    const int*   mask   = (const int*)d_in[7];

    float* out   = (float*)d_out;
    float* xnew  = out;                          // (B,T,2C)
    float* attn  = out + (size_t)B * T * C2;     // (B,T,T,HEADS)

    float *subj, *obj, *part;
    cudaGetSymbolAddress((void**)&subj, g_subj);
    cudaGetSymbolAddress((void**)&obj, g_obj);
    cudaGetSymbolAddress((void**)&part, g_part);

    pool_concat_kernel<<<(B * T * C2 + 255) / 256, 256>>>(x, xnew);

    dim3 gg(C / 32, (B * T) / 64, 2);   // (8, 32, 2) = 512 blocks
    gemm_kernel<<<gg, 128>>>(xnew, W_subj, b_subj, W_obj, b_obj, subj, obj);

    dim3 ga(NJT, T / TI, B);            // (16, 16, 4) = 1024 blocks
    rep_exp_kernel<<<ga, 64>>>(subj, obj, W_t, b_t, attn, part);

    normalize_kernel<<<B * T, 128>>>(part, mask, attn);
}

// round 6
// speedup vs baseline: 1.0901x; 1.0901x over previous
#include <cuda_runtime.h>
#include <cuda_bf16.h>
#include <math.h>

// Problem constants
#define B 4
#define T 512
#define C 256
#define C2 512
#define HEADS 4
#define MAXOFF 2

#define TI 32          // i-tile per block (rep)
#define TJ 64          // j-tile per block (rep)
#define NJT (T / TJ)   // 8 j-tiles
#define CK 128         // c chunk (rep)

typedef unsigned long long u64;

// Scratch (allocation-free: device globals)
__device__ float g_subj[B * T * C];
__device__ float g_obj[B * T * C];
__device__ float g_part[B * T * NJT * HEADS];   // partial exp-sums per j-tile

// packed f32x2 helpers
static __device__ __forceinline__ u64 add2(u64 a, u64 b) {
    u64 r; asm("add.rn.f32x2 %0, %1, %2;" : "=l"(r) : "l"(a), "l"(b)); return r;
}
static __device__ __forceinline__ u64 fma2(u64 a, u64 b, u64 c) {
    u64 r; asm("fma.rn.f32x2 %0, %1, %2, %3;" : "=l"(r) : "l"(a), "l"(b), "l"(c)); return r;
}
static __device__ __forceinline__ float2 unpack2(u64 v) {
    float2 r; asm("mov.b64 {%0, %1}, %2;" : "=f"(r.x), "=f"(r.y) : "l"(v)); return r;
}
#define FABS2(v) ((v) & 0x7fffffff7fffffffULL)

// ---------------------------------------------------------------------------
// Kernel 1: max-pool along channel (window 5, pad 2) + concat -> x_new
// ---------------------------------------------------------------------------
__global__ void pool_concat_kernel(const float* __restrict__ x,
                                   float* __restrict__ xnew) {
    int idx = blockIdx.x * 256 + threadIdx.x;
    if (idx >= B * T * C2) return;
    int cc = idx & (C2 - 1);
    int bt = idx >> 9;
    const float* xr = x + bt * C;
    float v;
    if (cc < C) {
        int lo = cc - MAXOFF; if (lo < 0) lo = 0;
        int hi = cc + MAXOFF; if (hi > C - 1) hi = C - 1;
        v = -INFINITY;
        #pragma unroll 5
        for (int c = lo; c <= hi; c++) v = fmaxf(v, xr[c]);
    } else {
        v = xr[cc - C];
    }
    xnew[idx] = v;
}

// ---------------------------------------------------------------------------
// Kernel 2: both projection GEMMs (R4 scalar version, known-good ~30us)
// out[M,N] = A[M,K] @ W[K,N] + bias[N];  M=2048, N=256, K=512.
// ---------------------------------------------------------------------------
__global__ void gemm_kernel(const float* __restrict__ A,
                            const float* __restrict__ W0,
                            const float* __restrict__ b0,
                            const float* __restrict__ W1,
                            const float* __restrict__ b1,
                            float* __restrict__ out0,
                            float* __restrict__ out1) {
    const int N = C;
    const int K = C2;

    const float* W    = blockIdx.z ? W1 : W0;
    const float* bias = blockIdx.z ? b1 : b0;
    float* out        = blockIdx.z ? out1 : out0;

    __shared__ float As[16][68];
    __shared__ float Ws[16][64];

    int tid = threadIdx.x;
    int tx = tid & 15;
    int ty = tid >> 4;
    int bm = blockIdx.y * 64;
    int bn = blockIdx.x * 64;

    float acc[4][4];
    #pragma unroll
    for (int i = 0; i < 4; i++)
        #pragma unroll
        for (int j = 0; j < 4; j++) acc[i][j] = 0.0f;

    for (int k0 = 0; k0 < K; k0 += 16) {
        #pragma unroll
        for (int l = 0; l < 4; l++) {
            int idx = tid + l * 256;
            int m = idx >> 4, ka = idx & 15;
            As[ka][m] = A[(bm + m) * K + k0 + ka];
            int n2 = idx & 63, kw = idx >> 6;
            Ws[kw][n2] = W[(k0 + kw) * N + bn + n2];
        }
        __syncthreads();
        #pragma unroll
        for (int k = 0; k < 16; k++) {
            float a[4], w[4];
            #pragma unroll
            for (int i = 0; i < 4; i++) a[i] = As[k][ty * 4 + i];
            float4 wv = *(const float4*)&Ws[k][tx * 4];
            w[0] = wv.x; w[1] = wv.y; w[2] = wv.z; w[3] = wv.w;
            #pragma unroll
            for (int i = 0; i < 4; i++)
                #pragma unroll
                for (int j = 0; j < 4; j++)
                    acc[i][j] += a[i] * w[j];
        }
        __syncthreads();
    }

    float4 bv = *(const float4*)&bias[bn + tx * 4];
    #pragma unroll
    for (int i = 0; i < 4; i++) {
        float4 o;
        o.x = acc[i][0] + bv.x;
        o.y = acc[i][1] + bv.y;
        o.z = acc[i][2] + bv.z;
        o.w = acc[i][3] + bv.w;
        *(float4*)&out[(bm + ty * 4 + i) * N + bn + tx * 4] = o;
    }
}

// ---------------------------------------------------------------------------
// Kernel 3a: e = exp(relu(rep)) for a 32i x 64j tile.
// 128 threads = 16 tx (j, stride-16) x 8 ty (i, stride-8).
// Microtile 4i x 4j x 4h; c packed f32x2. Swizzled conflict-free smem.
// ---------------------------------------------------------------------------
__global__ void __launch_bounds__(128)
rep_exp_kernel(const float* __restrict__ subj,
               const float* __restrict__ obj,
               const float* __restrict__ W_t,
               const float* __restrict__ b_t,
               float* __restrict__ attn,
               float* __restrict__ part) {
    __shared__ float s_sh[TJ * CK];     // [jrow][c], swizzled (32KB)
    __shared__ float o_sh[TI * CK];     // [irow][c], swizzled, holds -obj (16KB)
    __shared__ float w_sh[HEADS * C];   // [h][c] (4KB)

    const int tid = threadIdx.x;
    const int tx = tid & 15;           // j: j0 + tx + 16q
    const int ty = tid >> 4;           // i: i0 + ty + 8p   (0..7)
    const int jt = blockIdx.x;
    const int j0 = jt * TJ;
    const int i0 = blockIdx.y * TI;
    const int b  = blockIdx.z;

    // Load W_t transposed: w_sh[h][c] = W_t[c*4+h]
    #pragma unroll
    for (int c = tid; c < C; c += 128) {
        float4 wv = *(const float4*)&W_t[c * 4];
        w_sh[0 * C + c] = wv.x;
        w_sh[1 * C + c] = wv.y;
        w_sh[2 * C + c] = wv.z;
        w_sh[3 * C + c] = wv.w;
    }

    u64 acc[4][4][4];
    #pragma unroll
    for (int p = 0; p < 4; p++)
        #pragma unroll
        for (int q = 0; q < 4; q++)
            #pragma unroll
            for (int h = 0; h < 4; h++) acc[p][q][h] = 0ULL;

    const int swj = tx & 7;
    const float* sp[4];
    const float* op[4];
    #pragma unroll
    for (int q = 0; q < 4; q++) sp[q] = s_sh + (tx + 16 * q) * CK;
    #pragma unroll
    for (int p = 0; p < 4; p++) op[p] = o_sh + (ty + 8 * p) * CK;

    for (int ck = 0; ck < C / CK; ck++) {
        const int cbase = ck * CK;
        // load s chunk (64 rows x 128 c) and o chunk (32 rows x 128 c)
        #pragma unroll
        for (int l = 0; l < 16; l++) {
            int t = tid + l * 128;
            int row = t >> 5;          // 0..63
            int ccg = t & 31;
            int phys = (ccg ^ (row & 7)) << 2;
            float4 sv = *(const float4*)&subj[(b * T + j0 + row) * C + cbase + ccg * 4];
            *(float4*)&s_sh[row * CK + phys] = sv;
        }
        #pragma unroll
        for (int l = 0; l < 8; l++) {
            int t = tid + l * 128;
            int row = t >> 5;          // 0..31
            int ccg = t & 31;
            int phys = (ccg ^ (row & 7)) << 2;
            float4 ov = *(const float4*)&obj[(b * T + i0 + row) * C + cbase + ccg * 4];
            ov.x = -ov.x; ov.y = -ov.y; ov.z = -ov.z; ov.w = -ov.w;
            *(float4*)&o_sh[row * CK + phys] = ov;
        }
        __syncthreads();

        const float* wp0 = w_sh + 0 * C + cbase;
        const float* wp1 = w_sh + 1 * C + cbase;
        const float* wp2 = w_sh + 2 * C + cbase;
        const float* wp3 = w_sh + 3 * C + cbase;

        #pragma unroll 1
        for (int g = 0; g < CK / 4; g++) {
            const int gs = ((g ^ swj) << 2);
            const int gi = ((g ^ ty) << 2);
            ulonglong2 S[4], P[4], Wv[4];
            #pragma unroll
            for (int q = 0; q < 4; q++) S[q] = *(const ulonglong2*)(sp[q] + gs);
            #pragma unroll
            for (int p = 0; p < 4; p++) P[p] = *(const ulonglong2*)(op[p] + gi);
            Wv[0] = *(const ulonglong2*)(wp0 + g * 4);
            Wv[1] = *(const ulonglong2*)(wp1 + g * 4);
            Wv[2] = *(const ulonglong2*)(wp2 + g * 4);
            Wv[3] = *(const ulonglong2*)(wp3 + g * 4);

            #pragma unroll
            for (int p = 0; p < 4; p++) {
                #pragma unroll
                for (int q = 0; q < 4; q++) {
                    u64 a0 = FABS2(add2(S[q].x, P[p].x));
                    acc[p][q][0] = fma2(a0, Wv[0].x, acc[p][q][0]);
                    acc[p][q][1] = fma2(a0, Wv[1].x, acc[p][q][1]);
                    acc[p][q][2] = fma2(a0, Wv[2].x, acc[p][q][2]);
                    acc[p][q][3] = fma2(a0, Wv[3].x, acc[p][q][3]);
                    u64 a1 = FABS2(add2(S[q].y, P[p].y));
                    acc[p][q][0] = fma2(a1, Wv[0].y, acc[p][q][0]);
                    acc[p][q][1] = fma2(a1, Wv[1].y, acc[p][q][1]);
                    acc[p][q][2] = fma2(a1, Wv[2].y, acc[p][q][2]);
                    acc[p][q][3] = fma2(a1, Wv[3].y, acc[p][q][3]);
                }
            }
        }
        __syncthreads();
    }

    // Epilogue: z = relu(sum + bias), e = exp(z); write e; per-i partial sums
    const float4 btv = *(const float4*)b_t;

    #pragma unroll
    for (int p = 0; p < 4; p++) {
        int i = i0 + ty + 8 * p;
        float4 ps = make_float4(0.f, 0.f, 0.f, 0.f);
        #pragma unroll
        for (int q = 0; q < 4; q++) {
            int j = j0 + tx + 16 * q;
            float2 f0 = unpack2(acc[p][q][0]);
            float2 f1 = unpack2(acc[p][q][1]);
            float2 f2 = unpack2(acc[p][q][2]);
            float2 f3 = unpack2(acc[p][q][3]);
            float4 ev;
            ev.x = __expf(fmaxf(f0.x + f0.y + btv.x, 0.0f));
            ev.y = __expf(fmaxf(f1.x + f1.y + btv.y, 0.0f));
            ev.z = __expf(fmaxf(f2.x + f2.y + btv.z, 0.0f));
            ev.w = __expf(fmaxf(f3.x + f3.y + btv.w, 0.0f));
            *(float4*)&attn[(((size_t)(b * T + i)) * T + j) * HEADS] = ev;
            ps.x += ev.x; ps.y += ev.y; ps.z += ev.z; ps.w += ev.w;
        }
        // reduce across 16 tx lanes (tx = lane & 15 within warp)
        #pragma unroll
        for (int m = 8; m >= 1; m >>= 1) {
            ps.x += __shfl_xor_sync(0xffffffffu, ps.x, m);
            ps.y += __shfl_xor_sync(0xffffffffu, ps.y, m);
            ps.z += __shfl_xor_sync(0xffffffffu, ps.z, m);
            ps.w += __shfl_xor_sync(0xffffffffu, ps.w, m);
        }
        if (tx == 0)
            *(float4*)&part[((size_t)(b * T + i) * NJT + jt) * HEADS] = ps;
    }
}

// ---------------------------------------------------------------------------
// Kernel 3b: fused denominator + normalize + mask. One block per (b,i).
// ---------------------------------------------------------------------------
__global__ void __launch_bounds__(128)
normalize_kernel(const float* __restrict__ part,
                 const int* __restrict__ mask,
                 float* __restrict__ attn) {
    __shared__ float sinv[4];
    const int bi = blockIdx.x;         // b*T + i
    const int tid = threadIdx.x;

    if (tid < 4) {
        float s = 0.f;
        #pragma unroll
        for (int jt = 0; jt < NJT; jt++)
            s += part[((size_t)bi * NJT + jt) * HEADS + tid];
        sinv[tid] = 1.0f / s;
    }
    __syncthreads();

    const float4 iv = make_float4(sinv[0], sinv[1], sinv[2], sinv[3]);
    const int mi = mask[bi];
    const int b = bi >> 9;
    float4* arow = (float4*)attn + (size_t)bi * T;

    #pragma unroll
    for (int r = 0; r < 4; r++) {
        int j = tid + r * 128;
        float4 v = arow[j];
        int mj = mask[b * T + j];
        float kill = (mi && mj) ? 0.0f : 1.0f;
        v.x *= iv.x * kill;
        v.y *= iv.y * kill;
        v.z *= iv.z * kill;
        v.w *= iv.w * kill;
        arow[j] = v;
    }
}

// ---------------------------------------------------------------------------
extern "C" void kernel_launch(void* const* d_in, const int* in_sizes, int n_in,
                              void* d_out, int out_size) {
    const float* x      = (const float*)d_in[0];
    const float* W_subj = (const float*)d_in[1];
    const float* b_subj = (const float*)d_in[2];
    const float* W_obj  = (const float*)d_in[3];
    const float* b_obj  = (const float*)d_in[4];
    const float* W_t    = (const float*)d_in[5];
    const float* b_t    = (const float*)d_in[6];
    const int*   mask   = (const int*)d_in[7];

    float* out   = (float*)d_out;
    float* xnew  = out;                          // (B,T,2C)
    float* attn  = out + (size_t)B * T * C2;     // (B,T,T,HEADS)

    float *subj, *obj, *part;
    cudaGetSymbolAddress((void**)&subj, g_subj);
    cudaGetSymbolAddress((void**)&obj, g_obj);
    cudaGetSymbolAddress((void**)&part, g_part);

    pool_concat_kernel<<<(B * T * C2 + 255) / 256, 256>>>(x, xnew);

    dim3 gg(C / 64, (B * T) / 64, 2);   // (4, 32, 2)
    gemm_kernel<<<gg, 256>>>(xnew, W_subj, b_subj, W_obj, b_obj, subj, obj);

    dim3 ga(T / TJ, T / TI, B);         // (8, 16, 4) = 512 blocks
    rep_exp_kernel<<<ga, 128>>>(subj, obj, W_t, b_t, attn, part);

    normalize_kernel<<<B * T, 128>>>(part, mask, attn);
}